// round 16
// baseline (speedup 1.0000x reference)
#include <cuda_runtime.h>
#include <cuda_fp16.h>
#include <cstdint>

#define Bb 4
#define Tt 1024
#define Vv 32000
#define Ee 1024
#define Hh 16
#define HSs 64
#define Mm 4096  // B*T

// ---------------- scratch (static device globals) ---------------------------
__device__ __half g_xh[(size_t)Mm * Ee];
__device__ __half g_Wq[(size_t)3 * Ee * Ee];
__device__ __half g_qkh[(size_t)2 * 64 * Tt * HSs];  // [z][bh][t][d]
__device__ __half g_vth[(size_t)64 * HSs * Tt];      // [bh][d][t]  V^T hi
__device__ __half g_zh[(size_t)Mm * Ee];
__device__ __half g_Fh[(size_t)Ee * Ee];
__device__ __half g_Ahi[(size_t)Mm * Ee];
__device__ __half g_Bhi[(size_t)Vv * Ee];

// ===================== arch-neutral PTX helpers (sm_80+) ====================
__device__ __forceinline__ uint32_t smem_u32(const void* p) {
    uint32_t a;
    asm("{ .reg .u64 t; cvta.to.shared.u64 t, %1; cvt.u32.u64 %0, t; }"
        : "=r"(a) : "l"(p));
    return a;
}
__device__ __forceinline__ void ldsm4(uint32_t* r, uint32_t addr) {
    asm volatile("ldmatrix.sync.aligned.m8n8.x4.shared.b16 {%0,%1,%2,%3}, [%4];"
                 : "=r"(r[0]), "=r"(r[1]), "=r"(r[2]), "=r"(r[3]) : "r"(addr));
}
__device__ __forceinline__ void mma_fp16(float* c, const uint32_t* a,
                                         const uint32_t* b) {
    asm volatile(
        "mma.sync.aligned.m16n8k16.row.col.f32.f16.f16.f32 "
        "{%0,%1,%2,%3}, {%4,%5,%6,%7}, {%8,%9}, {%0,%1,%2,%3};"
        : "+f"(c[0]), "+f"(c[1]), "+f"(c[2]), "+f"(c[3])
        : "r"(a[0]), "r"(a[1]), "r"(a[2]), "r"(a[3]), "r"(b[0]), "r"(b[1]));
}
#define CP16(dst, src) \
    asm volatile("cp.async.cg.shared.global [%0], [%1], 16;" \
                 :: "r"(dst), "l"(src))
#define CP_COMMIT() asm volatile("cp.async.commit_group;" ::: "memory")
#define CP_WAIT1()  asm volatile("cp.async.wait_group 1;" ::: "memory")
#define CP_WAIT0()  asm volatile("cp.async.wait_group 0;" ::: "memory")

// ---------------- embed (hi only) --------------------------------------------
__global__ void embed_kernel(const int* __restrict__ inp,
                             const float* __restrict__ tok,
                             const float* __restrict__ pos) {
    int row = blockIdx.x;
    int t   = row & (Tt - 1);
    int id  = inp[row];
    const float4* te = (const float4*)(tok + (size_t)id * Ee);
    const float4* pe = (const float4*)(pos + (size_t)t * Ee);
    int i = threadIdx.x;
    float4 a = te[i], b = pe[i];
    __align__(8) __half h[4];
    h[0] = __float2half(a.x + b.x);
    h[1] = __float2half(a.y + b.y);
    h[2] = __float2half(a.z + b.z);
    h[3] = __float2half(a.w + b.w);
    *(uint2*)(g_xh + ((size_t)row << 10) + i * 4) = *(uint2*)h;
}

// ---------------- QKV weights -> [z*1024+h*64+d][e] fp16 hi ------------------
__global__ void wsplit_kernel(const float* __restrict__ Wk,
                              const float* __restrict__ Wq,
                              const float* __restrict__ Wv) {
    __shared__ float tile[64][65];
    int z = blockIdx.z;
    const float* W = (z == 0) ? Wk : (z == 1) ? Wq : Wv;
    int h  = blockIdx.x;
    int eb = blockIdx.y * 64;
    int tid = threadIdx.x;

    const float* Wh = W + (size_t)h * Ee * HSs;
    for (int i = tid; i < 1024; i += 256) {
        int r = i >> 4, c4 = i & 15;
        float4 v = *(const float4*)(Wh + (size_t)(eb + r) * HSs + c4 * 4);
        tile[c4 * 4 + 0][r] = v.x;
        tile[c4 * 4 + 1][r] = v.y;
        tile[c4 * 4 + 2][r] = v.z;
        tile[c4 * 4 + 3][r] = v.w;
    }
    __syncthreads();

    __half* oh = g_Wq + (size_t)z * Ee * Ee;
    for (int i = tid; i < 512; i += 256) {
        int d = i >> 3, c = i & 7;
        __align__(16) __half hb[8];
#pragma unroll
        for (int j = 0; j < 8; j++) hb[j] = __float2half(tile[d][c * 8 + j]);
        size_t dst = (size_t)(h * 64 + d) * Ee + eb + c * 8;
        *(uint4*)(oh + dst) = *(uint4*)hb;
    }
}

// ---------------- generic [K][N] fp32 -> [N][K] fp16 hi transpose ------------
__global__ void cvt_transpose_kernel(const float* __restrict__ W,
                                     __half* __restrict__ hi, int N) {
    __shared__ float tile[64][65];
    int nb = blockIdx.x * 64;
    int kb = blockIdx.y * 64;
    int tid = threadIdx.x;

    for (int i = tid; i < 1024; i += 256) {
        int r = i >> 4, c4 = i & 15;
        float4 v = *(const float4*)(W + (size_t)(kb + r) * N + nb + c4 * 4);
        tile[c4 * 4 + 0][r] = v.x;
        tile[c4 * 4 + 1][r] = v.y;
        tile[c4 * 4 + 2][r] = v.z;
        tile[c4 * 4 + 3][r] = v.w;
    }
    __syncthreads();

    for (int i = tid; i < 512; i += 256) {
        int nr = i >> 3, c = i & 7;
        __align__(16) __half hb[8];
#pragma unroll
        for (int j = 0; j < 8; j++) hb[j] = __float2half(tile[nr][c * 8 + j]);
        size_t dst = (size_t)(nb + nr) * Ee + kb + c * 8;
        *(uint4*)(hi + dst) = *(uint4*)hb;
    }
}

// ---------------- mma flash attention (R15, unchanged) -----------------------
#define RH 144
#define AT_QS   (128 * RH)
#define AT_KARR (64 * RH)
#define AT_STG  (2 * AT_KARR)
#define AT_SMEM (AT_QS + 3 * AT_STG)

__global__ __launch_bounds__(256, 2) void attn_kernel() {
    extern __shared__ __align__(128) char smem[];
    uint32_t sb = smem_u32(smem);

    int bh = blockIdx.x;
    int qt = (Tt / 128 - 1) - (int)blockIdx.y;
    int tid = threadIdx.x;
    int w = tid >> 5, lane = tid & 31;

    const __half* Qg = g_qkh + ((size_t)bh * Tt) * HSs;
    const __half* Kg = g_qkh + ((size_t)(64 + bh) * Tt) * HSs;
    const __half* Vh = g_vth + (size_t)bh * HSs * Tt;

    int nst = 2 * qt + 2;

    auto load_stage = [&](int st, int buf) {
        uint32_t base = sb + AT_QS + buf * AT_STG;
#pragma unroll
        for (int it = 0; it < 4; it++) {
            int i = tid + it * 256;
            int arr = i >> 9, rem = i & 511;
            int r = rem >> 3, c = rem & 7;
            uint32_t dst = base + arr * AT_KARR + r * RH + c * 16;
            const __half* src =
                (arr == 0) ? Kg + ((size_t)(st * 64 + r) << 6) + c * 8
                           : Vh + ((size_t)r << 10) + st * 64 + c * 8;
            CP16(dst, src);
        }
    };
#pragma unroll
    for (int it = 0; it < 4; it++) {
        int i = tid + it * 256;
        int r = i >> 3, c = i & 7;
        CP16(sb + r * RH + c * 16, Qg + ((size_t)(qt * 128 + r) << 6) + c * 8);
    }
    load_stage(0, 0);
    CP_COMMIT();
    if (nst > 1) { load_stage(1, 1); }
    CP_COMMIT();

    float O[8][4];
#pragma unroll
    for (int i = 0; i < 8; i++)
#pragma unroll
        for (int j = 0; j < 4; j++) O[i][j] = 0.f;
    float l0 = 0.f, l1 = 0.f;

    uint32_t aq[4][4];
    uint32_t a_off = (uint32_t)((w * 16 + (lane & 15)) * RH + (lane >> 4) * 16);
    uint32_t bo = (uint32_t)(((lane >> 4) * 8 + (lane & 7)) * RH +
                             ((lane >> 3) & 1) * 16);

    for (int st = 0; st < nst; st++) {
        if (st + 1 < nst) { CP_WAIT1(); } else { CP_WAIT0(); }
        __syncthreads();
        if (st + 2 < nst) {
            load_stage(st + 2, (st + 2) % 3);
            CP_COMMIT();
        }

        if (st == 0) {
#pragma unroll
            for (int ks = 0; ks < 4; ks++) ldsm4(aq[ks], sb + ks * 32 + a_off);
        }

        uint32_t kb = sb + AT_QS + (st % 3) * AT_STG;
        uint32_t vhb = kb + AT_KARR;

        float S[8][4];
#pragma unroll
        for (int i = 0; i < 8; i++)
#pragma unroll
            for (int j = 0; j < 4; j++) S[i][j] = 0.f;
#pragma unroll
        for (int ks = 0; ks < 4; ks++) {
            uint32_t bk[8][2];
#pragma unroll
            for (int p = 0; p < 4; p++)
                ldsm4(&bk[2 * p][0], kb + p * (16 * RH) + ks * 32 + bo);
#pragma unroll
            for (int nt = 0; nt < 8; nt++) mma_fp16(S[nt], aq[ks], bk[nt]);
        }

        bool dtile = (st >= 2 * qt);
        int r0 = qt * 128 + w * 16 + (lane >> 2);
        uint32_t pah[4][4];
#pragma unroll
        for (int nt = 0; nt < 8; nt++) {
            float p[4];
#pragma unroll
            for (int j = 0; j < 4; j++) {
                float x = S[nt][j] * 0.125f;
                float e = 1.f + x * (1.f + x * (0.5f + x * (0.166666667f +
                          x * 0.0416666667f)));
                if (dtile) {
                    int cs = st * 64 + nt * 8 + 2 * (lane & 3) + (j & 1);
                    int tr = r0 + ((j >> 1) ? 8 : 0);
                    if (cs > tr) e = 0.f;
                }
                p[j] = e;
            }
            l0 += p[0] + p[1];
            l1 += p[2] + p[3];
            __half h0 = __float2half(p[0]), h1 = __float2half(p[1]);
            __half h2 = __float2half(p[2]), h3 = __float2half(p[3]);
            int kv = nt >> 1, hi2 = (nt & 1) * 2;
            pah[kv][hi2 + 0] = __half_as_ushort(h0) |
                               ((uint32_t)__half_as_ushort(h1) << 16);
            pah[kv][hi2 + 1] = __half_as_ushort(h2) |
                               ((uint32_t)__half_as_ushort(h3) << 16);
        }

#pragma unroll
        for (int kv = 0; kv < 4; kv++) {
            uint32_t bv[8][2];
#pragma unroll
            for (int p = 0; p < 4; p++)
                ldsm4(&bv[2 * p][0], vhb + p * (16 * RH) + kv * 32 + bo);
#pragma unroll
            for (int dt = 0; dt < 8; dt++) mma_fp16(O[dt], pah[kv], bv[dt]);
        }
        __syncthreads();
    }

    const unsigned FULL = 0xffffffffu;
    l0 += __shfl_xor_sync(FULL, l0, 1); l0 += __shfl_xor_sync(FULL, l0, 2);
    l1 += __shfl_xor_sync(FULL, l1, 1); l1 += __shfl_xor_sync(FULL, l1, 2);
    float inv0 = 1.f / l0, inv1 = 1.f / l1;

    int b = bh >> 4, h = bh & 15;
    int t0 = qt * 128 + w * 16 + (lane >> 2);
#pragma unroll
    for (int dt = 0; dt < 8; dt++) {
        int d = h * HSs + dt * 8 + 2 * (lane & 3);
        __half h0 = __float2half(O[dt][0] * inv0);
        __half h1 = __float2half(O[dt][1] * inv0);
        size_t o0 = ((size_t)(b * Tt + t0) << 10) + d;
        *(uint32_t*)(g_zh + o0) = __half_as_ushort(h0) |
                                  ((uint32_t)__half_as_ushort(h1) << 16);
        h0 = __float2half(O[dt][2] * inv1);
        h1 = __float2half(O[dt][3] * inv1);
        size_t o1 = ((size_t)(b * Tt + t0 + 8) << 10) + d;
        *(uint32_t*)(g_zh + o1) = __half_as_ushort(h0) |
                                  ((uint32_t)__half_as_ushort(h1) << 16);
    }
}

// ---------------- fp16 1-pass mma GEMM, templated tile -----------------------
// NTILE in {128, 256}. MINB = min blocks/SM for launch_bounds.
// EPI: 0=logits fp32+bias (NTILE=256); 1=FF relu hi; 2=merged qkv (Q/K or V)
#define ROWB   144
#define ARR_A  (128 * ROWB)                  // 18432

template <int EPI, int NTILE, int MINB>
__global__ __launch_bounds__(256, MINB) void mk_mma_kernel(
    const __half* __restrict__ Ah, const __half* __restrict__ Bh,
    const float* __restrict__ bias, float* __restrict__ C,
    __half* __restrict__ Ch) {
    constexpr int ARR_B = NTILE * ROWB;
    constexpr int STG = ARR_A + ARR_B;
    constexpr int NWC = NTILE / 4;           // n cols per warp
    constexpr int NF = NTILE / 32;           // n8-frags per warp
    extern __shared__ __align__(128) char smem[];
    uint32_t sb = smem_u32(smem);

    int tid = threadIdx.x;
    int wid = tid >> 5, lane = tid & 31;
    int wm = wid & 1, wn = wid >> 1;
    int m0 = blockIdx.x * 128;
    int n0 = blockIdx.y * NTILE;

    uint32_t a_off = (uint32_t)((wm * 64 + (lane & 15)) * ROWB + (lane >> 4) * 16);
    uint32_t b_off = (uint32_t)((wn * NWC + ((lane >> 4) * 8) + (lane & 7)) * ROWB +
                                ((lane >> 3) & 1) * 16);

    float Cacc[4][NF][4];
#pragma unroll
    for (int i = 0; i < 4; i++)
#pragma unroll
        for (int j = 0; j < NF; j++)
#pragma unroll
            for (int k = 0; k < 4; k++) Cacc[i][j][k] = 0.f;

    auto load_stage = [&](int ch, int buf) {
        int k0 = ch * 64;
        uint32_t base = sb + buf * STG;
        constexpr int NCH = (128 + NTILE) * 8;   // 16B chunks
#pragma unroll
        for (int it = 0; it < NCH / 256; it++) {
            int i = tid + it * 256;
            int arr = (i >= 1024), rem = arr ? i - 1024 : i;
            int r = rem >> 3, c = rem & 7;
            uint32_t dst = base + arr * ARR_A + r * ROWB + c * 16;
            const __half* src =
                (arr == 0 ? Ah : Bh) +
                (((size_t)((arr == 0 ? m0 : n0) + r)) << 10) + k0 + c * 8;
            CP16(dst, src);
        }
    };

    load_stage(0, 0);
    CP_COMMIT();
    load_stage(1, 1);
    CP_COMMIT();
    for (int ch = 0; ch < 16; ch++) {
        if (ch < 15) { CP_WAIT1(); } else { CP_WAIT0(); }
        __syncthreads();
        if (ch + 2 < 16) {
            load_stage(ch + 2, (ch + 2) % 3);
            CP_COMMIT();
        }

        uint32_t sA = sb + (ch % 3) * STG;
        uint32_t sB = sA + ARR_A;
#pragma unroll
        for (int ks = 0; ks < 4; ks++) {
            uint32_t ah[4][4], bh[NF][2];
#pragma unroll
            for (int mt = 0; mt < 4; mt++)
                ldsm4(ah[mt], sA + mt * (16 * ROWB) + ks * 32 + a_off);
#pragma unroll
            for (int p = 0; p < NF / 2; p++)
                ldsm4(&bh[2 * p][0], sB + p * (16 * ROWB) + ks * 32 + b_off);
#pragma unroll
            for (int mt = 0; mt < 4; mt++)
#pragma unroll
                for (int nt = 0; nt < NF; nt++)
                    mma_fp16(Cacc[mt][nt], ah[mt], bh[nt]);
        }
    }

    int row0 = m0 + wm * 64;
    int col0 = n0 + wn * NWC;

    if (EPI == 2 && n0 >= 2048) {
        // ---- V epilogue: smem transpose -> coalesced hi stores ----
        __syncthreads();
        __half* sh = (__half*)smem;
#pragma unroll
        for (int mt = 0; mt < 4; mt++)
#pragma unroll
            for (int nt = 0; nt < NF; nt++) {
                int nl = wn * NWC + nt * 8 + 2 * (lane & 3);
#pragma unroll
                for (int hh = 0; hh < 2; hh++) {
                    int ml = wm * 64 + mt * 16 + (lane >> 2) + hh * 8;
                    sh[nl * 136 + ml] = __float2half(Cacc[mt][nt][hh * 2 + 0]);
                    sh[(nl + 1) * 136 + ml] =
                        __float2half(Cacc[mt][nt][hh * 2 + 1]);
                }
            }
        __syncthreads();
        int bq = m0 >> 10, tbase = m0 & 1023;
#pragma unroll
        for (int it = 0; it < 8; it++) {
            int i = tid + it * 256;
            int nl = i >> 4, c = i & 15;
            const __half* src = sh + nl * 136 + c * 8;
            int rn = (n0 + nl) & 1023;
            int hd = rn >> 6, d = rn & 63;
            size_t off = ((size_t)(bq * 16 + hd) * 64 + d) * 1024 + tbase + c * 8;
            *(uint4*)(g_vth + off) = *(const uint4*)src;
        }
        return;
    }

#pragma unroll
    for (int mt = 0; mt < 4; mt++) {
#pragma unroll
        for (int nt = 0; nt < NF; nt++) {
            int r = row0 + mt * 16 + (lane >> 2);
            int cn = col0 + nt * 8 + 2 * (lane & 3);
            if (EPI == 0) {
                float b0 = bias[cn], b1 = bias[cn + 1];
                float* p0 = C + (size_t)r * Vv + cn;
                p0[0] = Cacc[mt][nt][0] + b0;
                p0[1] = Cacc[mt][nt][1] + b1;
                float* p1 = C + (size_t)(r + 8) * Vv + cn;
                p1[0] = Cacc[mt][nt][2] + b0;
                p1[1] = Cacc[mt][nt][3] + b1;
            } else if (EPI == 1) {
                float b0 = bias[cn], b1 = bias[cn + 1];
#pragma unroll
                for (int hh = 0; hh < 2; hh++) {
                    float v0 = fmaxf(Cacc[mt][nt][hh * 2 + 0] + b0, 0.f);
                    float v1 = fmaxf(Cacc[mt][nt][hh * 2 + 1] + b1, 0.f);
                    __half h0 = __float2half(v0), h1 = __float2half(v1);
                    size_t o = ((size_t)(r + hh * 8) << 10) + cn;
                    *(uint32_t*)(Ch + o) =
                        __half_as_ushort(h0) |
                        ((uint32_t)__half_as_ushort(h1) << 16);
                }
            } else {  // EPI == 2, Q/K branch
#pragma unroll
                for (int hh = 0; hh < 2; hh++) {
                    int m = r + hh * 8;
                    int z = cn >> 10, rem = cn & 1023;
                    int hd = rem >> 6, d = rem & 63;
                    int bq = m >> 10, t = m & 1023;
                    int bhh = bq * 16 + hd;
                    __half a = __float2half(Cacc[mt][nt][hh * 2 + 0]);
                    __half bb = __float2half(Cacc[mt][nt][hh * 2 + 1]);
                    size_t o = (((size_t)z * 64 + bhh) * Tt + t) * HSs + d;
                    *(uint32_t*)(g_qkh + o) =
                        __half_as_ushort(a) |
                        ((uint32_t)__half_as_ushort(bb) << 16);
                }
            }
        }
    }
}

#define SM_128 (3 * (ARR_A + 128 * ROWB))    // 110592
#define SM_256 (3 * (ARR_A + 256 * ROWB))    // 165888

// ---------------- launch -----------------------------------------------------
extern "C" void kernel_launch(void* const* d_in, const int* in_sizes, int n_in,
                              void* d_out, int out_size) {
    (void)in_sizes; (void)n_in; (void)out_size;
    const int*   inp = (const int*)d_in[0];
    const float* tok = (const float*)d_in[1];
    const float* pos = (const float*)d_in[2];
    const float* Wk  = (const float*)d_in[3];
    const float* Wq  = (const float*)d_in[4];
    const float* Wv  = (const float*)d_in[5];
    const float* ffW = (const float*)d_in[6];
    const float* ffb = (const float*)d_in[7];
    const float* oW  = (const float*)d_in[8];
    const float* ob  = (const float*)d_in[9];
    float* out = (float*)d_out;

    void *pxh, *pwq, *pzh, *pfh, *pah, *pbh;
    cudaGetSymbolAddress(&pxh, g_xh);
    cudaGetSymbolAddress(&pwq, g_Wq);
    cudaGetSymbolAddress(&pzh, g_zh);
    cudaGetSymbolAddress(&pfh, g_Fh);
    cudaGetSymbolAddress(&pah, g_Ahi);
    cudaGetSymbolAddress(&pbh, g_Bhi);

    cudaFuncSetAttribute((const void*)mk_mma_kernel<0, 256, 1>,
                         cudaFuncAttributeMaxDynamicSharedMemorySize, SM_256);
    cudaFuncSetAttribute((const void*)mk_mma_kernel<1, 128, 2>,
                         cudaFuncAttributeMaxDynamicSharedMemorySize, SM_128);
    cudaFuncSetAttribute((const void*)mk_mma_kernel<2, 128, 2>,
                         cudaFuncAttributeMaxDynamicSharedMemorySize, SM_128);
    cudaFuncSetAttribute(attn_kernel,
                         cudaFuncAttributeMaxDynamicSharedMemorySize, AT_SMEM);

    embed_kernel<<<Mm, 256>>>(inp, tok, pos);
    wsplit_kernel<<<dim3(Hh, Ee / 64, 3), 256>>>(Wk, Wq, Wv);

    // QKV: single merged launch; epilogue branches Q/K vs V on n0
    mk_mma_kernel<2, 128, 2><<<dim3(Mm / 128, 24), 256, SM_128>>>(
        (const __half*)pxh, (const __half*)pwq, nullptr, nullptr, nullptr);

    attn_kernel<<<dim3(Bb * Hh, Tt / 128), 256, AT_SMEM>>>();

    cvt_transpose_kernel<<<dim3(Ee / 64, Ee / 64), 256>>>(
        ffW, (__half*)pfh, Ee);
    mk_mma_kernel<1, 128, 2><<<dim3(Mm / 128, Ee / 128), 256, SM_128>>>(
        (const __half*)pzh, (const __half*)pfh, ffb, nullptr, (__half*)pah);

    cvt_transpose_kernel<<<dim3(Vv / 64, Ee / 64), 256>>>(
        oW, (__half*)pbh, Vv);
    // logits: 128x256 tile, 3-stage, 1 CTA/SM
    mk_mma_kernel<0, 256, 1><<<dim3(Mm / 128, Vv / 256), 256, SM_256>>>(
        (const __half*)pah, (const __half*)pbh, ob, out, nullptr);
}

// round 17
// speedup vs baseline: 1.0763x; 1.0763x over previous
#include <cuda_runtime.h>
#include <cuda_fp16.h>
#include <cstdint>

#define Bb 4
#define Tt 1024
#define Vv 32000
#define Ee 1024
#define Hh 16
#define HSs 64
#define Mm 4096  // B*T

// ---------------- scratch (static device globals) ---------------------------
__device__ __half g_xh[(size_t)Mm * Ee];
__device__ __half g_Wq[(size_t)3 * Ee * Ee];
__device__ __half g_qkh[(size_t)2 * 64 * Tt * HSs];  // [z][bh][t][d]
__device__ __half g_vth[(size_t)64 * HSs * Tt];      // [bh][d][t]  V^T hi
__device__ __half g_zh[(size_t)Mm * Ee];
__device__ __half g_Fh[(size_t)Ee * Ee];
__device__ __half g_Ahi[(size_t)Mm * Ee];
__device__ __half g_Bhi[(size_t)Vv * Ee];

// ===================== arch-neutral PTX helpers (sm_80+) ====================
__device__ __forceinline__ uint32_t smem_u32(const void* p) {
    uint32_t a;
    asm("{ .reg .u64 t; cvta.to.shared.u64 t, %1; cvt.u32.u64 %0, t; }"
        : "=r"(a) : "l"(p));
    return a;
}
__device__ __forceinline__ void ldsm4(uint32_t* r, uint32_t addr) {
    asm volatile("ldmatrix.sync.aligned.m8n8.x4.shared.b16 {%0,%1,%2,%3}, [%4];"
                 : "=r"(r[0]), "=r"(r[1]), "=r"(r[2]), "=r"(r[3]) : "r"(addr));
}
__device__ __forceinline__ void mma_fp16(float* c, const uint32_t* a,
                                         const uint32_t* b) {
    asm volatile(
        "mma.sync.aligned.m16n8k16.row.col.f32.f16.f16.f32 "
        "{%0,%1,%2,%3}, {%4,%5,%6,%7}, {%8,%9}, {%0,%1,%2,%3};"
        : "+f"(c[0]), "+f"(c[1]), "+f"(c[2]), "+f"(c[3])
        : "r"(a[0]), "r"(a[1]), "r"(a[2]), "r"(a[3]), "r"(b[0]), "r"(b[1]));
}
#define CP16(dst, src) \
    asm volatile("cp.async.cg.shared.global [%0], [%1], 16;" \
                 :: "r"(dst), "l"(src))
#define CP_COMMIT() asm volatile("cp.async.commit_group;" ::: "memory")
#define CP_WAIT1()  asm volatile("cp.async.wait_group 1;" ::: "memory")
#define CP_WAIT0()  asm volatile("cp.async.wait_group 0;" ::: "memory")

// ---------------- embed (hi only) --------------------------------------------
__global__ void embed_kernel(const int* __restrict__ inp,
                             const float* __restrict__ tok,
                             const float* __restrict__ pos) {
    int row = blockIdx.x;
    int t   = row & (Tt - 1);
    int id  = inp[row];
    const float4* te = (const float4*)(tok + (size_t)id * Ee);
    const float4* pe = (const float4*)(pos + (size_t)t * Ee);
    int i = threadIdx.x;
    float4 a = te[i], b = pe[i];
    __align__(8) __half h[4];
    h[0] = __float2half(a.x + b.x);
    h[1] = __float2half(a.y + b.y);
    h[2] = __float2half(a.z + b.z);
    h[3] = __float2half(a.w + b.w);
    *(uint2*)(g_xh + ((size_t)row << 10) + i * 4) = *(uint2*)h;
}

// ---------------- QKV weights -> [z*1024+h*64+d][e] fp16 hi ------------------
__global__ void wsplit_kernel(const float* __restrict__ Wk,
                              const float* __restrict__ Wq,
                              const float* __restrict__ Wv) {
    __shared__ float tile[64][65];
    int z = blockIdx.z;
    const float* W = (z == 0) ? Wk : (z == 1) ? Wq : Wv;
    int h  = blockIdx.x;
    int eb = blockIdx.y * 64;
    int tid = threadIdx.x;

    const float* Wh = W + (size_t)h * Ee * HSs;
    for (int i = tid; i < 1024; i += 256) {
        int r = i >> 4, c4 = i & 15;
        float4 v = *(const float4*)(Wh + (size_t)(eb + r) * HSs + c4 * 4);
        tile[c4 * 4 + 0][r] = v.x;
        tile[c4 * 4 + 1][r] = v.y;
        tile[c4 * 4 + 2][r] = v.z;
        tile[c4 * 4 + 3][r] = v.w;
    }
    __syncthreads();

    __half* oh = g_Wq + (size_t)z * Ee * Ee;
    for (int i = tid; i < 512; i += 256) {
        int d = i >> 3, c = i & 7;
        __align__(16) __half hb[8];
#pragma unroll
        for (int j = 0; j < 8; j++) hb[j] = __float2half(tile[d][c * 8 + j]);
        size_t dst = (size_t)(h * 64 + d) * Ee + eb + c * 8;
        *(uint4*)(oh + dst) = *(uint4*)hb;
    }
}

// ---------------- generic [K][N] fp32 -> [N][K] fp16 hi transpose ------------
__global__ void cvt_transpose_kernel(const float* __restrict__ W,
                                     __half* __restrict__ hi, int N) {
    __shared__ float tile[64][65];
    int nb = blockIdx.x * 64;
    int kb = blockIdx.y * 64;
    int tid = threadIdx.x;

    for (int i = tid; i < 1024; i += 256) {
        int r = i >> 4, c4 = i & 15;
        float4 v = *(const float4*)(W + (size_t)(kb + r) * N + nb + c4 * 4);
        tile[c4 * 4 + 0][r] = v.x;
        tile[c4 * 4 + 1][r] = v.y;
        tile[c4 * 4 + 2][r] = v.z;
        tile[c4 * 4 + 3][r] = v.w;
    }
    __syncthreads();

    for (int i = tid; i < 512; i += 256) {
        int nr = i >> 3, c = i & 7;
        __align__(16) __half hb[8];
#pragma unroll
        for (int j = 0; j < 8; j++) hb[j] = __float2half(tile[nr][c * 8 + j]);
        size_t dst = (size_t)(nb + nr) * Ee + kb + c * 8;
        *(uint4*)(hi + dst) = *(uint4*)hb;
    }
}

// ---------------- mma flash attention (R15, unchanged) -----------------------
#define RH 144
#define AT_QS   (128 * RH)
#define AT_KARR (64 * RH)
#define AT_STG  (2 * AT_KARR)
#define AT_SMEM (AT_QS + 3 * AT_STG)

__global__ __launch_bounds__(256, 2) void attn_kernel() {
    extern __shared__ __align__(128) char smem[];
    uint32_t sb = smem_u32(smem);

    int bh = blockIdx.x;
    int qt = (Tt / 128 - 1) - (int)blockIdx.y;
    int tid = threadIdx.x;
    int w = tid >> 5, lane = tid & 31;

    const __half* Qg = g_qkh + ((size_t)bh * Tt) * HSs;
    const __half* Kg = g_qkh + ((size_t)(64 + bh) * Tt) * HSs;
    const __half* Vh = g_vth + (size_t)bh * HSs * Tt;

    int nst = 2 * qt + 2;

    auto load_stage = [&](int st, int buf) {
        uint32_t base = sb + AT_QS + buf * AT_STG;
#pragma unroll
        for (int it = 0; it < 4; it++) {
            int i = tid + it * 256;
            int arr = i >> 9, rem = i & 511;
            int r = rem >> 3, c = rem & 7;
            uint32_t dst = base + arr * AT_KARR + r * RH + c * 16;
            const __half* src =
                (arr == 0) ? Kg + ((size_t)(st * 64 + r) << 6) + c * 8
                           : Vh + ((size_t)r << 10) + st * 64 + c * 8;
            CP16(dst, src);
        }
    };
#pragma unroll
    for (int it = 0; it < 4; it++) {
        int i = tid + it * 256;
        int r = i >> 3, c = i & 7;
        CP16(sb + r * RH + c * 16, Qg + ((size_t)(qt * 128 + r) << 6) + c * 8);
    }
    load_stage(0, 0);
    CP_COMMIT();
    if (nst > 1) { load_stage(1, 1); }
    CP_COMMIT();

    float O[8][4];
#pragma unroll
    for (int i = 0; i < 8; i++)
#pragma unroll
        for (int j = 0; j < 4; j++) O[i][j] = 0.f;
    float l0 = 0.f, l1 = 0.f;

    uint32_t aq[4][4];
    uint32_t a_off = (uint32_t)((w * 16 + (lane & 15)) * RH + (lane >> 4) * 16);
    uint32_t bo = (uint32_t)(((lane >> 4) * 8 + (lane & 7)) * RH +
                             ((lane >> 3) & 1) * 16);

    for (int st = 0; st < nst; st++) {
        if (st + 1 < nst) { CP_WAIT1(); } else { CP_WAIT0(); }
        __syncthreads();
        if (st + 2 < nst) {
            load_stage(st + 2, (st + 2) % 3);
            CP_COMMIT();
        }

        if (st == 0) {
#pragma unroll
            for (int ks = 0; ks < 4; ks++) ldsm4(aq[ks], sb + ks * 32 + a_off);
        }

        uint32_t kb = sb + AT_QS + (st % 3) * AT_STG;
        uint32_t vhb = kb + AT_KARR;

        float S[8][4];
#pragma unroll
        for (int i = 0; i < 8; i++)
#pragma unroll
            for (int j = 0; j < 4; j++) S[i][j] = 0.f;
#pragma unroll
        for (int ks = 0; ks < 4; ks++) {
            uint32_t bk[8][2];
#pragma unroll
            for (int p = 0; p < 4; p++)
                ldsm4(&bk[2 * p][0], kb + p * (16 * RH) + ks * 32 + bo);
#pragma unroll
            for (int nt = 0; nt < 8; nt++) mma_fp16(S[nt], aq[ks], bk[nt]);
        }

        bool dtile = (st >= 2 * qt);
        int r0 = qt * 128 + w * 16 + (lane >> 2);
        uint32_t pah[4][4];
#pragma unroll
        for (int nt = 0; nt < 8; nt++) {
            float p[4];
#pragma unroll
            for (int j = 0; j < 4; j++) {
                float x = S[nt][j] * 0.125f;
                float e = 1.f + x * (1.f + x * (0.5f + x * (0.166666667f +
                          x * 0.0416666667f)));
                if (dtile) {
                    int cs = st * 64 + nt * 8 + 2 * (lane & 3) + (j & 1);
                    int tr = r0 + ((j >> 1) ? 8 : 0);
                    if (cs > tr) e = 0.f;
                }
                p[j] = e;
            }
            l0 += p[0] + p[1];
            l1 += p[2] + p[3];
            __half h0 = __float2half(p[0]), h1 = __float2half(p[1]);
            __half h2 = __float2half(p[2]), h3 = __float2half(p[3]);
            int kv = nt >> 1, hi2 = (nt & 1) * 2;
            pah[kv][hi2 + 0] = __half_as_ushort(h0) |
                               ((uint32_t)__half_as_ushort(h1) << 16);
            pah[kv][hi2 + 1] = __half_as_ushort(h2) |
                               ((uint32_t)__half_as_ushort(h3) << 16);
        }

#pragma unroll
        for (int kv = 0; kv < 4; kv++) {
            uint32_t bv[8][2];
#pragma unroll
            for (int p = 0; p < 4; p++)
                ldsm4(&bv[2 * p][0], vhb + p * (16 * RH) + kv * 32 + bo);
#pragma unroll
            for (int dt = 0; dt < 8; dt++) mma_fp16(O[dt], pah[kv], bv[dt]);
        }
        __syncthreads();
    }

    const unsigned FULL = 0xffffffffu;
    l0 += __shfl_xor_sync(FULL, l0, 1); l0 += __shfl_xor_sync(FULL, l0, 2);
    l1 += __shfl_xor_sync(FULL, l1, 1); l1 += __shfl_xor_sync(FULL, l1, 2);
    float inv0 = 1.f / l0, inv1 = 1.f / l1;

    int b = bh >> 4, h = bh & 15;
    int t0 = qt * 128 + w * 16 + (lane >> 2);
#pragma unroll
    for (int dt = 0; dt < 8; dt++) {
        int d = h * HSs + dt * 8 + 2 * (lane & 3);
        __half h0 = __float2half(O[dt][0] * inv0);
        __half h1 = __float2half(O[dt][1] * inv0);
        size_t o0 = ((size_t)(b * Tt + t0) << 10) + d;
        *(uint32_t*)(g_zh + o0) = __half_as_ushort(h0) |
                                  ((uint32_t)__half_as_ushort(h1) << 16);
        h0 = __float2half(O[dt][2] * inv1);
        h1 = __float2half(O[dt][3] * inv1);
        size_t o1 = ((size_t)(b * Tt + t0 + 8) << 10) + d;
        *(uint32_t*)(g_zh + o1) = __half_as_ushort(h0) |
                                  ((uint32_t)__half_as_ushort(h1) << 16);
    }
}

// ---------------- fp16 1-pass mma GEMM: 128x128, 3-stage, 2 CTAs/SM ----------
// NSWAP: if true, n tile index comes from blockIdx.x (n-fast grid order).
// EPI: 0=logits fp32+bias; 1=FF relu hi out; 2=Q/K fp16 strided;
//      3=V smem-transposed hi out
#define ROWB   144
#define ARR_A  (128 * ROWB)                  // 18432
#define STG1   (2 * ARR_A)                   // 36864 {A, B}
#define SM_TOT (3 * STG1)                    // 110592

template <int EPI, bool NSWAP>
__global__ __launch_bounds__(256, 2) void mk_mma_kernel(
    const __half* __restrict__ Ah, const __half* __restrict__ Bh,
    const float* __restrict__ bias, float* __restrict__ C,
    __half* __restrict__ Ch, int nbase) {
    extern __shared__ __align__(128) char smem[];
    uint32_t sb = smem_u32(smem);

    int tid = threadIdx.x;
    int wid = tid >> 5, lane = tid & 31;
    int wm = wid & 1, wn = wid >> 1;
    int m0 = (NSWAP ? blockIdx.y : blockIdx.x) * 128;
    int n0 = (NSWAP ? blockIdx.x : blockIdx.y) * 128 + nbase;

    uint32_t a_off = (uint32_t)((wm * 64 + (lane & 15)) * ROWB + (lane >> 4) * 16);
    uint32_t b_off = (uint32_t)((wn * 32 + ((lane >> 4) * 8) + (lane & 7)) * ROWB +
                                ((lane >> 3) & 1) * 16);

    float Cacc[4][4][4];
#pragma unroll
    for (int i = 0; i < 4; i++)
#pragma unroll
        for (int j = 0; j < 4; j++)
#pragma unroll
            for (int k = 0; k < 4; k++) Cacc[i][j][k] = 0.f;

    auto load_stage = [&](int ch, int buf) {
        int k0 = ch * 64;
        uint32_t base = sb + buf * STG1;
#pragma unroll
        for (int it = 0; it < 8; it++) {
            int i = tid + it * 256;
            int arr = i >> 10, rem = i & 1023;
            int r = rem >> 3, c = rem & 7;
            uint32_t dst = base + arr * ARR_A + r * ROWB + c * 16;
            const __half* src =
                (arr == 0 ? Ah : Bh) +
                (((size_t)((arr == 0 ? m0 : n0) + r)) << 10) + k0 + c * 8;
            CP16(dst, src);
        }
    };

    load_stage(0, 0);
    CP_COMMIT();
    load_stage(1, 1);
    CP_COMMIT();
    for (int ch = 0; ch < 16; ch++) {
        if (ch < 15) { CP_WAIT1(); } else { CP_WAIT0(); }
        __syncthreads();
        if (ch + 2 < 16) {
            load_stage(ch + 2, (ch + 2) % 3);
            CP_COMMIT();
        }

        uint32_t sA = sb + (ch % 3) * STG1;
        uint32_t sB = sA + ARR_A;
#pragma unroll
        for (int ks = 0; ks < 4; ks++) {
            uint32_t ah[4][4], bh[4][2];
#pragma unroll
            for (int mt = 0; mt < 4; mt++)
                ldsm4(ah[mt], sA + mt * (16 * ROWB) + ks * 32 + a_off);
#pragma unroll
            for (int p = 0; p < 2; p++)
                ldsm4(&bh[2 * p][0], sB + p * (16 * ROWB) + ks * 32 + b_off);
#pragma unroll
            for (int mt = 0; mt < 4; mt++)
#pragma unroll
                for (int nt = 0; nt < 4; nt++) mma_fp16(Cacc[mt][nt], ah[mt], bh[nt]);
        }
    }

    int row0 = m0 + wm * 64;
    int col0 = n0 + wn * 32;

    if (EPI == 3) {
        // ---- V epilogue: smem transpose -> coalesced hi stores ----
        __syncthreads();
        __half* sh = (__half*)smem;
#pragma unroll
        for (int mt = 0; mt < 4; mt++)
#pragma unroll
            for (int nt = 0; nt < 4; nt++) {
                int nl = wn * 32 + nt * 8 + 2 * (lane & 3);
#pragma unroll
                for (int hh = 0; hh < 2; hh++) {
                    int ml = wm * 64 + mt * 16 + (lane >> 2) + hh * 8;
                    sh[nl * 136 + ml] = __float2half(Cacc[mt][nt][hh * 2 + 0]);
                    sh[(nl + 1) * 136 + ml] =
                        __float2half(Cacc[mt][nt][hh * 2 + 1]);
                }
            }
        __syncthreads();
        int bq = m0 >> 10, tbase = m0 & 1023;
#pragma unroll
        for (int it = 0; it < 8; it++) {
            int i = tid + it * 256;
            int nl = i >> 4, c = i & 15;
            const __half* src = sh + nl * 136 + c * 8;
            int rn = (n0 + nl) & 1023;
            int hd = rn >> 6, d = rn & 63;
            size_t off = ((size_t)(bq * 16 + hd) * 64 + d) * 1024 + tbase + c * 8;
            *(uint4*)(g_vth + off) = *(const uint4*)src;
        }
        return;
    }

#pragma unroll
    for (int mt = 0; mt < 4; mt++) {
#pragma unroll
        for (int nt = 0; nt < 4; nt++) {
            int r = row0 + mt * 16 + (lane >> 2);
            int cn = col0 + nt * 8 + 2 * (lane & 3);
            if (EPI == 0) {
                float b0 = bias[cn], b1 = bias[cn + 1];
                float* p0 = C + (size_t)r * Vv + cn;
                p0[0] = Cacc[mt][nt][0] + b0;
                p0[1] = Cacc[mt][nt][1] + b1;
                float* p1 = C + (size_t)(r + 8) * Vv + cn;
                p1[0] = Cacc[mt][nt][2] + b0;
                p1[1] = Cacc[mt][nt][3] + b1;
            } else if (EPI == 1) {
                float b0 = bias[cn], b1 = bias[cn + 1];
#pragma unroll
                for (int hh = 0; hh < 2; hh++) {
                    float v0 = fmaxf(Cacc[mt][nt][hh * 2 + 0] + b0, 0.f);
                    float v1 = fmaxf(Cacc[mt][nt][hh * 2 + 1] + b1, 0.f);
                    __half h0 = __float2half(v0), h1 = __float2half(v1);
                    size_t o = ((size_t)(r + hh * 8) << 10) + cn;
                    *(uint32_t*)(Ch + o) =
                        __half_as_ushort(h0) |
                        ((uint32_t)__half_as_ushort(h1) << 16);
                }
            } else {  // EPI == 2: Q/K fp16
#pragma unroll
                for (int hh = 0; hh < 2; hh++) {
                    int m = r + hh * 8;
                    int z = cn >> 10, rem = cn & 1023;
                    int hd = rem >> 6, d = rem & 63;
                    int bq = m >> 10, t = m & 1023;
                    int bhh = bq * 16 + hd;
                    __half a = __float2half(Cacc[mt][nt][hh * 2 + 0]);
                    __half bb = __float2half(Cacc[mt][nt][hh * 2 + 1]);
                    size_t o = (((size_t)z * 64 + bhh) * Tt + t) * HSs + d;
                    *(uint32_t*)(g_qkh + o) =
                        __half_as_ushort(a) |
                        ((uint32_t)__half_as_ushort(bb) << 16);
                }
            }
        }
    }
}

// ---------------- launch -----------------------------------------------------
extern "C" void kernel_launch(void* const* d_in, const int* in_sizes, int n_in,
                              void* d_out, int out_size) {
    (void)in_sizes; (void)n_in; (void)out_size;
    const int*   inp = (const int*)d_in[0];
    const float* tok = (const float*)d_in[1];
    const float* pos = (const float*)d_in[2];
    const float* Wk  = (const float*)d_in[3];
    const float* Wq  = (const float*)d_in[4];
    const float* Wv  = (const float*)d_in[5];
    const float* ffW = (const float*)d_in[6];
    const float* ffb = (const float*)d_in[7];
    const float* oW  = (const float*)d_in[8];
    const float* ob  = (const float*)d_in[9];
    float* out = (float*)d_out;

    void *pxh, *pwq, *pzh, *pfh, *pah, *pbh;
    cudaGetSymbolAddress(&pxh, g_xh);
    cudaGetSymbolAddress(&pwq, g_Wq);
    cudaGetSymbolAddress(&pzh, g_zh);
    cudaGetSymbolAddress(&pfh, g_Fh);
    cudaGetSymbolAddress(&pah, g_Ahi);
    cudaGetSymbolAddress(&pbh, g_Bhi);

    cudaFuncSetAttribute((const void*)mk_mma_kernel<0, true>,
                         cudaFuncAttributeMaxDynamicSharedMemorySize, SM_TOT);
    cudaFuncSetAttribute((const void*)mk_mma_kernel<1, false>,
                         cudaFuncAttributeMaxDynamicSharedMemorySize, SM_TOT);
    cudaFuncSetAttribute((const void*)mk_mma_kernel<2, false>,
                         cudaFuncAttributeMaxDynamicSharedMemorySize, SM_TOT);
    cudaFuncSetAttribute((const void*)mk_mma_kernel<3, false>,
                         cudaFuncAttributeMaxDynamicSharedMemorySize, SM_TOT);
    cudaFuncSetAttribute(attn_kernel,
                         cudaFuncAttributeMaxDynamicSharedMemorySize, AT_SMEM);

    embed_kernel<<<Mm, 256>>>(inp, tok, pos);
    wsplit_kernel<<<dim3(Hh, Ee / 64, 3), 256>>>(Wk, Wq, Wv);

    // QKV: Q/K (n in [0,2048)), V (n in [2048,3072)), 1-pass hi (R15 split)
    mk_mma_kernel<2, false><<<dim3(Mm / 128, 16), 256, SM_TOT>>>(
        (const __half*)pxh, (const __half*)pwq, nullptr, nullptr, nullptr, 0);
    mk_mma_kernel<3, false><<<dim3(Mm / 128, 8), 256, SM_TOT>>>(
        (const __half*)pxh, (const __half*)pwq, nullptr, nullptr, nullptr, 2048);

    attn_kernel<<<dim3(Bb * Hh, Tt / 128), 256, AT_SMEM>>>();

    cvt_transpose_kernel<<<dim3(Ee / 64, Ee / 64), 256>>>(
        ffW, (__half*)pfh, Ee);
    mk_mma_kernel<1, false><<<dim3(Mm / 128, Ee / 128), 256, SM_TOT>>>(
        (const __half*)pzh, (const __half*)pfh, ffb, nullptr, (__half*)pah, 0);

    cvt_transpose_kernel<<<dim3(Vv / 64, Ee / 64), 256>>>(
        oW, (__half*)pbh, Vv);
    // logits: 128x128, 2 CTAs/SM (R15 config), n-fast grid order
    mk_mma_kernel<0, true><<<dim3(Vv / 128, Mm / 128), 256, SM_TOT>>>(
        (const __half*)pah, (const __half*)pbh, ob, out, nullptr, 0);
}